// round 7
// baseline (speedup 1.0000x reference)
#include <cuda_runtime.h>
#include <cstdint>

#define Nn  50000
#define NTt 300000
#define RPk 16
#define Ee  32
#define Cc  32

// ------------------------- device scratch (static, no allocs) -------------
__device__ float g_lat1[(size_t)NTt * RPk];        // 19.2 MB
__device__ float g_lat2[(size_t)NTt * RPk];        // 19.2 MB
__device__ float g_colsum[Nn * RPk];               // 3.2 MB
__device__ float g_rowsum[Nn * RPk];               // 3.2 MB
__device__ float g_h[Nn * Ee];                     // 6.4 MB
__device__ float g_h2[(size_t)RPk * Nn * Ee];      // 102.4 MB
__device__ int   g_deg_s[Nn];
__device__ int   g_deg_o[Nn];
__device__ int   g_off_s[Nn];
__device__ int   g_off_o[Nn];
__device__ int   g_cur_s[Nn];
__device__ int   g_cur_o[Nn];
__device__ int   g_perm_s[NTt];
__device__ int   g_perm_o[NTt];
__device__ int   g_counter[2];

// ------------------------- constant-memory weights ------------------------
__constant__ float cW1a[64 * 64];
__constant__ float cW1b[64 * 16];
__constant__ float cb1a[64];
__constant__ float cb1b[16];
__constant__ float cW2a[64 * 64];
__constant__ float cW2b[64 * 16];
__constant__ float cb2a[64];
__constant__ float cb2b[16];

// ------------------------- small helpers ----------------------------------
typedef unsigned long long ULL;
union F4U { float4 f; ULL u[2]; float s[4]; };
union F2U { float2 f; ULL u; float s[2]; };

__device__ __forceinline__ ULL splat2(float v) {
    ULL r;
    asm("mov.b64 %0, {%1, %1};" : "=l"(r) : "f"(v));
    return r;
}
__device__ __forceinline__ ULL ffma2(ULL a, ULL b, ULL c) {
    ULL d;
    asm("fma.rn.f32x2 %0, %1, %2, %3;" : "=l"(d) : "l"(a), "l"(b), "l"(c));
    return d;
}
__device__ __forceinline__ void red4(float4* a, float4 v) {
    asm volatile("red.global.add.v4.f32 [%0], {%1, %2, %3, %4};"
                 :: "l"(a), "f"(v.x), "f"(v.y), "f"(v.z), "f"(v.w) : "memory");
}
__device__ __forceinline__ void red1(float* a, float v) {
    asm volatile("red.global.add.f32 [%0], %1;" :: "l"(a), "f"(v) : "memory");
}

// ------------------------- init: zero scratch -----------------------------
__global__ void k_init() {
    size_t i = (size_t)blockIdx.x * blockDim.x + threadIdx.x;
    size_t stride = (size_t)gridDim.x * blockDim.x;
    float4 z = make_float4(0.f, 0.f, 0.f, 0.f);
    for (size_t p = i; p < (size_t)RPk * Nn * Ee / 4; p += stride)
        ((float4*)g_h2)[p] = z;
    for (size_t p = i; p < (size_t)Nn * RPk / 4; p += stride) {
        ((float4*)g_colsum)[p] = z;
        ((float4*)g_rowsum)[p] = z;
    }
    for (size_t p = i; p < (size_t)Nn * Ee / 4; p += stride)
        ((float4*)g_h)[p] = z;
    for (size_t p = i; p < Nn / 4; p += stride) {
        ((int4*)g_deg_s)[p] = make_int4(0, 0, 0, 0);
        ((int4*)g_deg_o)[p] = make_int4(0, 0, 0, 0);
    }
    if (i == 0) { g_counter[0] = 0; g_counter[1] = 0; }
}

// ------------------------- degree count -----------------------------------
__global__ void k_deg(const int* __restrict__ s_idx, const int* __restrict__ o_idx) {
    int t = blockIdx.x * blockDim.x + threadIdx.x;
    if (t < NTt) {
        atomicAdd(&g_deg_s[s_idx[t]], 1);
        atomicAdd(&g_deg_o[o_idx[t]], 1);
    }
}

// ---------------- CSR range allocation (warp-aggregated, unordered) -------
__global__ void k_alloc() {
    int i = blockIdx.x * blockDim.x + threadIdx.x;
    int lane = threadIdx.x & 31;
    int ds = (i < Nn) ? g_deg_s[i] : 0;
    int dq = (i < Nn) ? g_deg_o[i] : 0;
    int ss = ds, so = dq;
#pragma unroll
    for (int off = 1; off < 32; off <<= 1) {
        int a = __shfl_up_sync(0xffffffffu, ss, off);
        int b = __shfl_up_sync(0xffffffffu, so, off);
        if (lane >= off) { ss += a; so += b; }
    }
    int bs = 0, bo = 0;
    if (lane == 31) {
        bs = atomicAdd(&g_counter[0], ss);
        bo = atomicAdd(&g_counter[1], so);
    }
    bs = __shfl_sync(0xffffffffu, bs, 31);
    bo = __shfl_sync(0xffffffffu, bo, 31);
    if (i < Nn) {
        int es = bs + ss - ds;
        int eo = bo + so - dq;
        g_off_s[i] = es; g_cur_s[i] = es;
        g_off_o[i] = eo; g_cur_o[i] = eo;
    }
}

// --------- fused double-MLP + softmax + segment sums (one kernel) ---------
// block = 128 edges, 256 threads. Weights in __constant__.
// smem (floats): X[128][68] @0 ; H[128][68] @8704 (reused as lat[128][17]); red @17408
#define SM_X    0
#define SM_H    8704
#define SM_RED  17408
#define SM_FLOATS 17416

__device__ __forceinline__ void softmax16(float* l) {
    float m = l[0];
#pragma unroll
    for (int k = 1; k < 16; k++) m = fmaxf(m, l[k]);
    float s = 0.f;
#pragma unroll
    for (int k = 0; k < 16; k++) { l[k] = __expf(l[k] - m); s += l[k]; }
    float inv = 1.f / s;
#pragma unroll
    for (int k = 0; k < 16; k++) l[k] *= inv;
}

template<int L>
__device__ __forceinline__ ULL ldWa(int i) {     // 2 consecutive Wa floats
    F2U r;
    r.f = (L == 1) ? *(const float2*)&cW1a[i] : *(const float2*)&cW2a[i];
    return r.u;
}
template<int L>
__device__ __forceinline__ ULL ldWb(int i) {
    F2U r;
    r.f = (L == 1) ? *(const float2*)&cW1b[i] : *(const float2*)&cW2b[i];
    return r.u;
}
template<int L>
__device__ __forceinline__ ULL ldba(int i) {
    F2U r;
    r.f = (L == 1) ? *(const float2*)&cb1a[i] : *(const float2*)&cb2a[i];
    return r.u;
}
template<int L>
__device__ __forceinline__ ULL ldbb(int i) {
    F2U r;
    r.f = (L == 1) ? *(const float2*)&cb1b[i] : *(const float2*)&cb2b[i];
    return r.u;
}

template<int L>
__device__ __forceinline__ void mlp_layer(float* sm, int tid, int e_base,
                                          const int* __restrict__ nidx,
                                          float* __restrict__ lat_out,
                                          float* __restrict__ sum_out) {
    int lane = tid & 31, wq = tid >> 5;

    // ---- phase 1: H[128][64] = relu(X @ Wa + ba); thread: 4 edges x 8 hid --
    {
        int h0 = wq * 8;
        ULL acc[4][4];
        ULL b0 = ldba<L>(h0);
        ULL b1 = ldba<L>(h0 + 2);
        ULL b2 = ldba<L>(h0 + 4);
        ULL b3 = ldba<L>(h0 + 6);
#pragma unroll
        for (int i = 0; i < 4; i++) {
            acc[i][0] = b0; acc[i][1] = b1; acc[i][2] = b2; acc[i][3] = b3;
        }
        const float4* X4 = (const float4*)(sm + SM_X);
#pragma unroll 2
        for (int k4 = 0; k4 < 16; k4++) {
            float4 xv0 = X4[lane * 17 + k4];
            float4 xv1 = X4[(lane + 32) * 17 + k4];
            float4 xv2 = X4[(lane + 64) * 17 + k4];
            float4 xv3 = X4[(lane + 96) * 17 + k4];
#pragma unroll
            for (int u = 0; u < 4; u++) {
                int k = k4 * 4 + u;
                ULL w0 = ldWa<L>(k * 64 + h0);
                ULL w1 = ldWa<L>(k * 64 + h0 + 2);
                ULL w2 = ldWa<L>(k * 64 + h0 + 4);
                ULL w3 = ldWa<L>(k * 64 + h0 + 6);
                float f0 = (&xv0.x)[u], f1 = (&xv1.x)[u];
                float f2 = (&xv2.x)[u], f3 = (&xv3.x)[u];
                ULL s0 = splat2(f0), s1 = splat2(f1), s2 = splat2(f2), s3 = splat2(f3);
                acc[0][0] = ffma2(s0, w0, acc[0][0]);
                acc[0][1] = ffma2(s0, w1, acc[0][1]);
                acc[0][2] = ffma2(s0, w2, acc[0][2]);
                acc[0][3] = ffma2(s0, w3, acc[0][3]);
                acc[1][0] = ffma2(s1, w0, acc[1][0]);
                acc[1][1] = ffma2(s1, w1, acc[1][1]);
                acc[1][2] = ffma2(s1, w2, acc[1][2]);
                acc[1][3] = ffma2(s1, w3, acc[1][3]);
                acc[2][0] = ffma2(s2, w0, acc[2][0]);
                acc[2][1] = ffma2(s2, w1, acc[2][1]);
                acc[2][2] = ffma2(s2, w2, acc[2][2]);
                acc[2][3] = ffma2(s2, w3, acc[2][3]);
                acc[3][0] = ffma2(s3, w0, acc[3][0]);
                acc[3][1] = ffma2(s3, w1, acc[3][1]);
                acc[3][2] = ffma2(s3, w2, acc[3][2]);
                acc[3][3] = ffma2(s3, w3, acc[3][3]);
            }
        }
        // relu + store H as 2x STS.128 per edge (pad 68 = 17 float4)
        float4* H4 = (float4*)(sm + SM_H);
#pragma unroll
        for (int i = 0; i < 4; i++) {
            float2 v0 = *(float2*)&acc[i][0];
            float2 v1 = *(float2*)&acc[i][1];
            float2 v2 = *(float2*)&acc[i][2];
            float2 v3 = *(float2*)&acc[i][3];
            float4 lo = make_float4(fmaxf(v0.x, 0.f), fmaxf(v0.y, 0.f),
                                    fmaxf(v1.x, 0.f), fmaxf(v1.y, 0.f));
            float4 hi = make_float4(fmaxf(v2.x, 0.f), fmaxf(v2.y, 0.f),
                                    fmaxf(v3.x, 0.f), fmaxf(v3.y, 0.f));
            H4[(lane + 32 * i) * 17 + wq * 2]     = lo;
            H4[(lane + 32 * i) * 17 + wq * 2 + 1] = hi;
        }
    }
    __syncthreads();

    // ---- phase 2: lat[128][16] = H @ Wb + bb; thread: 1 edge x 8 classes --
    int e = tid & 127, ch = tid >> 7;
    int c0 = ch * 8;
    {
        ULL a2[4];
        a2[0] = ldbb<L>(c0);
        a2[1] = ldbb<L>(c0 + 2);
        a2[2] = ldbb<L>(c0 + 4);
        a2[3] = ldbb<L>(c0 + 6);
        const float4* H4 = (const float4*)(sm + SM_H);
#pragma unroll 4
        for (int j4 = 0; j4 < 16; j4++) {
            float4 hv = H4[e * 17 + j4];
#pragma unroll
            for (int u = 0; u < 4; u++) {
                int j = j4 * 4 + u;
                ULL s = splat2((&hv.x)[u]);
                a2[0] = ffma2(s, ldWb<L>(j * 16 + c0),     a2[0]);
                a2[1] = ffma2(s, ldWb<L>(j * 16 + c0 + 2), a2[1]);
                a2[2] = ffma2(s, ldWb<L>(j * 16 + c0 + 4), a2[2]);
                a2[3] = ffma2(s, ldWb<L>(j * 16 + c0 + 6), a2[3]);
            }
        }
        __syncthreads();   // all H reads done before lat overlays H region
        float* lr = sm + SM_H + e * 17 + c0;
#pragma unroll
        for (int q = 0; q < 4; q++) {
            float2 v = *(float2*)&a2[q];
            lr[2 * q] = v.x; lr[2 * q + 1] = v.y;
        }
    }
    __syncthreads();

    // ---- epilogue: softmax, emit latents, segment-sum atomics ----
    float part = 0.f;
    if (tid < 128 && e_base + tid < NTt) {
        int ed = e_base + tid;
        float l[16];
        const float* lr = sm + SM_H + tid * 17;
#pragma unroll
        for (int c = 0; c < 16; c++) l[c] = lr[c];
        softmax16(l);
        float4* po = (float4*)(lat_out + (size_t)ed * 16);
#pragma unroll
        for (int q = 0; q < 4; q++)
            po[q] = make_float4(l[4 * q], l[4 * q + 1], l[4 * q + 2], l[4 * q + 3]);
        int ix = nidx[ed];
#pragma unroll
        for (int k = 1; k < 16; k++)
            red1(&sum_out[ix * k], l[k]);
        part = l[0];
    }
#pragma unroll
    for (int off = 16; off; off >>= 1)
        part += __shfl_down_sync(0xffffffffu, part, off);
    if ((tid & 31) == 0) sm[SM_RED + (tid >> 5)] = part;
    __syncthreads();
    if (tid == 0) {
        float a = 0.f;
#pragma unroll
        for (int i = 0; i < 8; i++) a += sm[SM_RED + i];
        red1(&sum_out[0], a);
    }
    __syncthreads();   // lat region (H) free before next layer writes H
}

__global__ void __launch_bounds__(256, 3)
k_mlp(const int* __restrict__ s_idx, const int* __restrict__ o_idx,
      const float* __restrict__ nhots,
      float* __restrict__ lat1, float* __restrict__ lat2,
      float* __restrict__ colsum, float* __restrict__ rowsum) {
    extern __shared__ __align__(16) float sm[];
    int tid = threadIdx.x;
    int e_base = blockIdx.x * 128;

    // ---- stage X [128 edges][64], pad 68 (17 float4) ----
    float4* X4 = (float4*)(sm + SM_X);
#pragma unroll
    for (int j = 0; j < 8; j++) {
        int idx4 = tid + 256 * j;            // 0..2047 float4 slots
        int e = idx4 >> 4, kq = idx4 & 15;
        float4 v = make_float4(0.f, 0.f, 0.f, 0.f);
        if (e_base + e < NTt)
            v = __ldg((const float4*)(nhots + (size_t)(e_base + e) * 64) + kq);
        X4[e * 17 + kq] = v;
    }
    __syncthreads();

    mlp_layer<1>(sm, tid, e_base, o_idx, lat1, colsum);
    mlp_layer<2>(sm, tid, e_base, s_idx, lat2, rowsum);
}

__global__ void k_scatter(const int* __restrict__ s_idx,
                          const int* __restrict__ o_idx) {
    int t = blockIdx.x * blockDim.x + threadIdx.x;
    if (t < NTt) {
        int s = s_idx[t], o = o_idx[t];
        g_perm_s[atomicAdd(&g_cur_s[s], 1)] = t;
        g_perm_o[atomicAdd(&g_cur_o[o], 1)] = t;
    }
}

// ------ layer-1 spmm, warp per o: weights loaded once, red into h[s] ------
__global__ void __launch_bounds__(256)
k_spmm1(const int* __restrict__ s_idx, const float* __restrict__ w1) {
    int w = (blockIdx.x * blockDim.x + threadIdx.x) >> 5;
    int lane = threadIdx.x & 31;
    if (w >= Nn) return;
    int o = w;
    int deg = g_deg_o[o];
    if (deg == 0) return;
    int beg = g_off_o[o], end = beg + deg;

    float wk[16];
#pragma unroll
    for (int k = 0; k < 16; k++) {
        int j = o * k;
        float c = g_colsum[j];                 // uniform across warp -> broadcast
        float inv = (c > 0.f) ? __frcp_rn(c) : 0.f;
        wk[k] = w1[(size_t)j * 32 + lane] * inv;
    }

    int t = __ldg(&g_perm_o[beg]);
    for (int p = beg; p < end; p++) {
        int tn = (p + 1 < end) ? __ldg(&g_perm_o[p + 1]) : t;  // prefetch next idx
        int s = __ldg(&s_idx[t]);
        float lv = (lane < 16) ? __ldg(&g_lat1[(size_t)t * 16 + lane]) : 0.f;
        float acc = 0.f;
#pragma unroll
        for (int k = 0; k < 16; k++)
            acc += __shfl_sync(0xffffffffu, lv, k) * wk[k];
        red1(&g_h[s * 32 + lane], acc);
        t = tn;
    }
}

// ------------------------- h = relu(h + bias1) -----------------------------
__global__ void k_relu(const float* __restrict__ bias1) {
    int i = blockIdx.x * blockDim.x + threadIdx.x;
    if (i < Nn * Ee)
        g_h[i] = fmaxf(g_h[i] + bias1[i & 31], 0.f);
}

// -------- h2 row j=0 (k=0 bin): block-aggregated global reduction ---------
__global__ void __launch_bounds__(256)
k_h2k0(const int* __restrict__ o_idx) {
    __shared__ float sacc[8][32];
    int lane = threadIdx.x & 31, wid = threadIdx.x >> 5;
    int gw = blockIdx.x * 8 + wid;
    int nw = gridDim.x * 8;
    float acc = 0.f;
    for (int t = gw; t < NTt; t += nw) {
        float l0 = __ldg(&g_lat2[(size_t)t * 16]);
        int o = __ldg(&o_idx[t]);
        acc += l0 * g_h[o * 32 + lane];
    }
    sacc[wid][lane] = acc;
    __syncthreads();
    if (wid == 0) {
        float tot = 0.f;
#pragma unroll
        for (int i = 0; i < 8; i++) tot += sacc[i][lane];
        red1(&g_h2[lane], tot);
    }
}

// --------------- layer-2 spmm into h2 (warp per s, k>=1 only) -------------
__global__ void __launch_bounds__(256)
k_spmm2(const int* __restrict__ o_idx) {
    __shared__ __align__(16) float stage[8][16 * 32];
    int wid = threadIdx.x >> 5, lane = threadIdx.x & 31;
    int s = blockIdx.x * 8 + wid;
    if (s >= Nn) return;
    int deg = g_deg_s[s];
    if (deg == 0) return;
    int beg = g_off_s[s], end = beg + deg;
    float acc[16];
#pragma unroll
    for (int k = 0; k < 16; k++) acc[k] = 0.f;
    int t = __ldg(&g_perm_s[beg]);
    for (int p = beg; p < end; p++) {
        int tn = (p + 1 < end) ? __ldg(&g_perm_s[p + 1]) : t;  // prefetch next idx
        int o = __ldg(&o_idx[t]);
        float lv = (lane < 16) ? __ldg(&g_lat2[(size_t)t * 16 + lane]) : 0.f;
        float hv = g_h[o * 32 + lane];
#pragma unroll
        for (int k = 1; k < 16; k++)
            acc[k] += __shfl_sync(0xffffffffu, lv, k) * hv;
        t = tn;
    }
    float* st = stage[wid];
#pragma unroll
    for (int k = 1; k < 16; k++) st[k * 32 + lane] = acc[k];
    __syncwarp();
#pragma unroll
    for (int it = 0; it < 4; it++) {
        int idx = it * 32 + lane;        // 0..127 over 16 rows x 8 float4
        if (idx >= 8) {                  // skip k=0 (handled by k_h2k0)
            int k = idx >> 3, q = idx & 7;
            float4 v = ((float4*)st)[idx];
            int j = s * k;
            red4(&((float4*)g_h2)[(size_t)j * 8 + q], v);
        }
    }
}

// ------------------- einsum + bias2: out, 2 nodes / thread ----------------
__global__ void __launch_bounds__(256)
k_out(const float* __restrict__ w2, const float* __restrict__ bias2,
      float* __restrict__ out) {
    extern __shared__ __align__(16) float sw2[];   // 16*32*32 floats = 64 KB
    for (int i = threadIdx.x; i < 16 * 32 * 32; i += 256) sw2[i] = w2[i];
    __syncthreads();
    int n0 = blockIdx.x * 256 + threadIdx.x;       // 0..24999
    if (n0 >= Nn / 2) return;
    int n1 = n0 + Nn / 2;
    ULL accA[16], accB[16];
#pragma unroll
    for (int c2 = 0; c2 < 16; c2++) {
        accA[c2] = ((const ULL*)bias2)[c2];
        accB[c2] = accA[c2];
    }
#pragma unroll 1
    for (int r = 0; r < 16; r++) {
        int jA = r * Nn + n0;
        int jB = jA + Nn / 2;
        float ra = g_rowsum[jA], rb = g_rowsum[jB];
        float invA = (ra > 0.f) ? __frcp_rn(ra) : 0.f;
        float invB = (rb > 0.f) ? __frcp_rn(rb) : 0.f;
        const float4* hA = (const float4*)&g_h2[(size_t)jA * 32];
        const float4* hB = (const float4*)&g_h2[(size_t)jB * 32];
#pragma unroll
        for (int e4 = 0; e4 < 8; e4++) {
            float4 va = hA[e4];
            float4 vb = hB[e4];
            float xa[4] = { va.x * invA, va.y * invA, va.z * invA, va.w * invA };
            float xb[4] = { vb.x * invB, vb.y * invB, vb.z * invB, vb.w * invB };
#pragma unroll
            for (int u = 0; u < 4; u++) {
                int e = e4 * 4 + u;
                ULL sa = splat2(xa[u]);
                ULL sb = splat2(xb[u]);
                const float4* wr4 = (const float4*)&sw2[(r * 32 + e) * 32];
#pragma unroll
                for (int c4 = 0; c4 < 8; c4++) {
                    F4U w; w.f = wr4[c4];
                    accA[2 * c4]     = ffma2(sa, w.u[0], accA[2 * c4]);
                    accA[2 * c4 + 1] = ffma2(sa, w.u[1], accA[2 * c4 + 1]);
                    accB[2 * c4]     = ffma2(sb, w.u[0], accB[2 * c4]);
                    accB[2 * c4 + 1] = ffma2(sb, w.u[1], accB[2 * c4 + 1]);
                }
            }
        }
    }
    ULL* opA = (ULL*)(out + (size_t)n0 * 32);
    ULL* opB = (ULL*)(out + (size_t)n1 * 32);
#pragma unroll
    for (int c2 = 0; c2 < 16; c2++) { opA[c2] = accA[c2]; opB[c2] = accB[c2]; }
}

// ------------------------- launch -----------------------------------------
extern "C" void kernel_launch(void* const* d_in, const int* in_sizes, int n_in,
                              void* d_out, int out_size) {
    const int*   s_idx = (const int*)d_in[0];
    const int*   o_idx = (const int*)d_in[1];
    const float* nhots = (const float*)d_in[2];
    const float* W1a   = (const float*)d_in[3];
    const float* b1a   = (const float*)d_in[4];
    const float* W1b   = (const float*)d_in[5];
    const float* b1b   = (const float*)d_in[6];
    const float* W2a   = (const float*)d_in[7];
    const float* b2a   = (const float*)d_in[8];
    const float* W2b   = (const float*)d_in[9];
    const float* b2b   = (const float*)d_in[10];
    const float* w1    = (const float*)d_in[11];
    const float* w2    = (const float*)d_in[12];
    const float* bias1 = (const float*)d_in[13];
    const float* bias2 = (const float*)d_in[14];
    float* out = (float*)d_out;

    static float* lat1p = nullptr;
    static float* lat2p = nullptr;
    static float* colp = nullptr;
    static float* rowp = nullptr;
    if (!lat1p) {
        cudaGetSymbolAddress((void**)&lat1p, g_lat1);
        cudaGetSymbolAddress((void**)&lat2p, g_lat2);
        cudaGetSymbolAddress((void**)&colp, g_colsum);
        cudaGetSymbolAddress((void**)&rowp, g_rowsum);
        cudaFuncSetAttribute(k_mlp, cudaFuncAttributeMaxDynamicSharedMemorySize,
                             SM_FLOATS * (int)sizeof(float));
        cudaFuncSetAttribute(k_out, cudaFuncAttributeMaxDynamicSharedMemorySize,
                             16 * 32 * 32 * (int)sizeof(float));
    }

    // stage weights into constant memory (async D2D, graph-capturable)
    cudaMemcpyToSymbolAsync(cW1a, W1a, 4096 * sizeof(float), 0, cudaMemcpyDeviceToDevice);
    cudaMemcpyToSymbolAsync(cW1b, W1b, 1024 * sizeof(float), 0, cudaMemcpyDeviceToDevice);
    cudaMemcpyToSymbolAsync(cb1a, b1a, 64 * sizeof(float), 0, cudaMemcpyDeviceToDevice);
    cudaMemcpyToSymbolAsync(cb1b, b1b, 16 * sizeof(float), 0, cudaMemcpyDeviceToDevice);
    cudaMemcpyToSymbolAsync(cW2a, W2a, 4096 * sizeof(float), 0, cudaMemcpyDeviceToDevice);
    cudaMemcpyToSymbolAsync(cW2b, W2b, 1024 * sizeof(float), 0, cudaMemcpyDeviceToDevice);
    cudaMemcpyToSymbolAsync(cb2a, b2a, 64 * sizeof(float), 0, cudaMemcpyDeviceToDevice);
    cudaMemcpyToSymbolAsync(cb2b, b2b, 16 * sizeof(float), 0, cudaMemcpyDeviceToDevice);

    int mlp_blocks = (NTt + 127) / 128;
    size_t mlp_smem = SM_FLOATS * sizeof(float);

    k_init<<<2048, 256>>>();                                   // 0
    k_deg<<<(NTt + 255) / 256, 256>>>(s_idx, o_idx);           // 1
    k_alloc<<<(Nn + 255) / 256, 256>>>();                      // 2
    k_mlp<<<mlp_blocks, 256, mlp_smem>>>(s_idx, o_idx, nhots,  // 3 <- ncu slot
                                         lat1p, lat2p, colp, rowp);
    k_scatter<<<(NTt + 255) / 256, 256>>>(s_idx, o_idx);       // 4
    k_spmm1<<<(Nn * 32 + 255) / 256, 256>>>(s_idx, w1);        // 5
    k_relu<<<(Nn * Ee + 255) / 256, 256>>>(bias1);             // 6
    k_h2k0<<<512, 256>>>(o_idx);                               // 7
    k_spmm2<<<(Nn + 7) / 8, 256>>>(o_idx);                     // 8
    k_out<<<(Nn / 2 + 255) / 256, 256, 16 * 32 * 32 * (int)sizeof(float)>>>(w2, bias2, out); // 9
}

// round 8
// speedup vs baseline: 1.1556x; 1.1556x over previous
#include <cuda_runtime.h>
#include <cstdint>

#define Nn  50000
#define NTt 300000
#define RPk 16
#define Ee  32
#define Cc  32

// ------------------------- device scratch (static, no allocs) -------------
__device__ float g_lat1[(size_t)NTt * RPk];        // 19.2 MB
__device__ float g_lat2[(size_t)NTt * RPk];        // 19.2 MB
__device__ float g_colsum[Nn * RPk];               // 3.2 MB
__device__ float g_rowsum[Nn * RPk];               // 3.2 MB
__device__ float g_h[Nn * Ee];                     // 6.4 MB
__device__ float g_h2[(size_t)RPk * Nn * Ee];      // 102.4 MB
__device__ int   g_deg_s[Nn];
__device__ int   g_deg_o[Nn];
__device__ int   g_off_s[Nn];
__device__ int   g_off_o[Nn];
__device__ int   g_cur_s[Nn];
__device__ int   g_cur_o[Nn];
__device__ int   g_perm_s[NTt];
__device__ int   g_perm_o[NTt];
__device__ int   g_counter[2];

// ------------------------- small helpers ----------------------------------
typedef unsigned long long ULL;
union F4U { float4 f; ULL u[2]; float s[4]; };

__device__ __forceinline__ ULL splat2(float v) {
    ULL r;
    asm("mov.b64 %0, {%1, %1};" : "=l"(r) : "f"(v));
    return r;
}
__device__ __forceinline__ ULL ffma2(ULL a, ULL b, ULL c) {
    ULL d;
    asm("fma.rn.f32x2 %0, %1, %2, %3;" : "=l"(d) : "l"(a), "l"(b), "l"(c));
    return d;
}
__device__ __forceinline__ void red4(float4* a, float4 v) {
    asm volatile("red.global.add.v4.f32 [%0], {%1, %2, %3, %4};"
                 :: "l"(a), "f"(v.x), "f"(v.y), "f"(v.z), "f"(v.w) : "memory");
}
__device__ __forceinline__ void red1(float* a, float v) {
    asm volatile("red.global.add.f32 [%0], %1;" :: "l"(a), "f"(v) : "memory");
}

// ------------------------- init: zero scratch -----------------------------
__global__ void k_init() {
    size_t i = (size_t)blockIdx.x * blockDim.x + threadIdx.x;
    size_t stride = (size_t)gridDim.x * blockDim.x;
    float4 z = make_float4(0.f, 0.f, 0.f, 0.f);
    for (size_t p = i; p < (size_t)RPk * Nn * Ee / 4; p += stride)
        ((float4*)g_h2)[p] = z;
    for (size_t p = i; p < (size_t)Nn * RPk / 4; p += stride) {
        ((float4*)g_colsum)[p] = z;
        ((float4*)g_rowsum)[p] = z;
    }
    for (size_t p = i; p < (size_t)Nn * Ee / 4; p += stride)
        ((float4*)g_h)[p] = z;
    for (size_t p = i; p < Nn / 4; p += stride) {
        ((int4*)g_deg_s)[p] = make_int4(0, 0, 0, 0);
        ((int4*)g_deg_o)[p] = make_int4(0, 0, 0, 0);
    }
    if (i == 0) { g_counter[0] = 0; g_counter[1] = 0; }
}

// ------------------------- degree count -----------------------------------
__global__ void k_deg(const int* __restrict__ s_idx, const int* __restrict__ o_idx) {
    int t = blockIdx.x * blockDim.x + threadIdx.x;
    if (t < NTt) {
        atomicAdd(&g_deg_s[s_idx[t]], 1);
        atomicAdd(&g_deg_o[o_idx[t]], 1);
    }
}

// ---------------- CSR range allocation (warp-aggregated, unordered) -------
__global__ void k_alloc() {
    int i = blockIdx.x * blockDim.x + threadIdx.x;
    int lane = threadIdx.x & 31;
    int ds = (i < Nn) ? g_deg_s[i] : 0;
    int dq = (i < Nn) ? g_deg_o[i] : 0;
    int ss = ds, so = dq;
#pragma unroll
    for (int off = 1; off < 32; off <<= 1) {
        int a = __shfl_up_sync(0xffffffffu, ss, off);
        int b = __shfl_up_sync(0xffffffffu, so, off);
        if (lane >= off) { ss += a; so += b; }
    }
    int bs = 0, bo = 0;
    if (lane == 31) {
        bs = atomicAdd(&g_counter[0], ss);
        bo = atomicAdd(&g_counter[1], so);
    }
    bs = __shfl_sync(0xffffffffu, bs, 31);
    bo = __shfl_sync(0xffffffffu, bo, 31);
    if (i < Nn) {
        int es = bs + ss - ds;
        int eo = bo + so - dq;
        g_off_s[i] = es; g_cur_s[i] = es;
        g_off_o[i] = eo; g_cur_o[i] = eo;
    }
}

// --------- fused double-MLP + softmax + segment sums (one kernel) ---------
// block = 128 edges, 256 threads. smem layout (floats):
//   X    [128][65] @ 0      (8320)
//   H    [128][67] @ 8320   (8576)  -- reused for lat[128][17] per layer
//   W1   [64][64]  @ 16896  (4096)
//   W1b  [64][16]  @ 20992  (1024)
//   W2   [64][64]  @ 22016  (4096)
//   W2b  [64][16]  @ 26112  (1024)
//   B    ba1/bb1/ba2/bb2 @ 27136 (160)
//   red  @ 27296 (8)
#define SM_X    0
#define SM_H    8320
#define SM_W1   16896
#define SM_W1b  20992
#define SM_W2   22016
#define SM_W2b  26112
#define SM_BA1  27136
#define SM_BB1  27200
#define SM_BA2  27216
#define SM_BB2  27280
#define SM_RED  27296
#define SM_FLOATS 27304

__device__ __forceinline__ void softmax16(float* l) {
    float m = l[0];
#pragma unroll
    for (int k = 1; k < 16; k++) m = fmaxf(m, l[k]);
    float s = 0.f;
#pragma unroll
    for (int k = 0; k < 16; k++) { l[k] = __expf(l[k] - m); s += l[k]; }
    float inv = 1.f / s;
#pragma unroll
    for (int k = 0; k < 16; k++) l[k] *= inv;
}

__device__ __forceinline__ void mlp_layer(float* sm, int tid, int e_base,
                                          const float* sW, const float* sWb,
                                          const float* sba, const float* sbb,
                                          const int* __restrict__ nidx,
                                          float* __restrict__ lat_out,
                                          float* __restrict__ sum_out) {
    int lane = tid & 31, wq = tid >> 5;

    // ---- phase 1: H[128][64] = relu(X @ Wa + ba); thread: 4 edges x 8 hid --
    {
        int h0 = wq * 8;
        ULL acc[4][4];
        ULL b0 = *(ULL*)&sba[h0];
        ULL b1 = *(ULL*)&sba[h0 + 2];
        ULL b2 = *(ULL*)&sba[h0 + 4];
        ULL b3 = *(ULL*)&sba[h0 + 6];
#pragma unroll
        for (int i = 0; i < 4; i++) {
            acc[i][0] = b0; acc[i][1] = b1; acc[i][2] = b2; acc[i][3] = b3;
        }
#pragma unroll 2
        for (int k = 0; k < 64; k++) {
            float x0 = sm[SM_X + lane * 65 + k];
            float x1 = sm[SM_X + (lane + 32) * 65 + k];
            float x2 = sm[SM_X + (lane + 64) * 65 + k];
            float x3 = sm[SM_X + (lane + 96) * 65 + k];
            F4U wA; wA.f = *(const float4*)&sW[k * 64 + h0];
            F4U wB; wB.f = *(const float4*)&sW[k * 64 + h0 + 4];
            ULL s0 = splat2(x0), s1 = splat2(x1), s2 = splat2(x2), s3 = splat2(x3);
            acc[0][0] = ffma2(s0, wA.u[0], acc[0][0]);
            acc[0][1] = ffma2(s0, wA.u[1], acc[0][1]);
            acc[0][2] = ffma2(s0, wB.u[0], acc[0][2]);
            acc[0][3] = ffma2(s0, wB.u[1], acc[0][3]);
            acc[1][0] = ffma2(s1, wA.u[0], acc[1][0]);
            acc[1][1] = ffma2(s1, wA.u[1], acc[1][1]);
            acc[1][2] = ffma2(s1, wB.u[0], acc[1][2]);
            acc[1][3] = ffma2(s1, wB.u[1], acc[1][3]);
            acc[2][0] = ffma2(s2, wA.u[0], acc[2][0]);
            acc[2][1] = ffma2(s2, wA.u[1], acc[2][1]);
            acc[2][2] = ffma2(s2, wB.u[0], acc[2][2]);
            acc[2][3] = ffma2(s2, wB.u[1], acc[2][3]);
            acc[3][0] = ffma2(s3, wA.u[0], acc[3][0]);
            acc[3][1] = ffma2(s3, wA.u[1], acc[3][1]);
            acc[3][2] = ffma2(s3, wB.u[0], acc[3][2]);
            acc[3][3] = ffma2(s3, wB.u[1], acc[3][3]);
        }
        // relu + store H (pad 67)
#pragma unroll
        for (int i = 0; i < 4; i++) {
            float* hr = sm + SM_H + (lane + 32 * i) * 67 + h0;
#pragma unroll
            for (int q = 0; q < 4; q++) {
                float2 v = *(float2*)&acc[i][q];
                hr[2 * q]     = fmaxf(v.x, 0.f);
                hr[2 * q + 1] = fmaxf(v.y, 0.f);
            }
        }
    }
    __syncthreads();

    // ---- phase 2: lat[128][16] = H @ Wb + bb; thread: 4 edges x 2 classes --
    {
        int c0 = wq * 2;
        ULL a2[4];
        ULL binit = *(ULL*)&sbb[c0];
#pragma unroll
        for (int i = 0; i < 4; i++) a2[i] = binit;
#pragma unroll 2
        for (int j = 0; j < 64; j++) {
            float h0v = sm[SM_H + lane * 67 + j];
            float h1v = sm[SM_H + (lane + 32) * 67 + j];
            float h2v = sm[SM_H + (lane + 64) * 67 + j];
            float h3v = sm[SM_H + (lane + 96) * 67 + j];
            ULL wb = *(const ULL*)&sWb[j * 16 + c0];
            a2[0] = ffma2(splat2(h0v), wb, a2[0]);
            a2[1] = ffma2(splat2(h1v), wb, a2[1]);
            a2[2] = ffma2(splat2(h2v), wb, a2[2]);
            a2[3] = ffma2(splat2(h3v), wb, a2[3]);
        }
        __syncthreads();   // all H reads done before lat overlays H region
#pragma unroll
        for (int i = 0; i < 4; i++) {
            float2 v = *(float2*)&a2[i];
            float* lr = sm + SM_H + (lane + 32 * i) * 17 + c0;
            lr[0] = v.x; lr[1] = v.y;
        }
    }
    __syncthreads();

    // ---- epilogue: softmax, emit latents, segment-sum atomics ----
    float part = 0.f;
    if (tid < 128 && e_base + tid < NTt) {
        int e = e_base + tid;
        float l[16];
        const float* lr = sm + SM_H + tid * 17;
#pragma unroll
        for (int c = 0; c < 16; c++) l[c] = lr[c];
        softmax16(l);
        float4* po = (float4*)(lat_out + (size_t)e * 16);
#pragma unroll
        for (int q = 0; q < 4; q++)
            po[q] = make_float4(l[4 * q], l[4 * q + 1], l[4 * q + 2], l[4 * q + 3]);
        int ix = nidx[e];
#pragma unroll
        for (int k = 1; k < 16; k++)
            red1(&sum_out[ix * k], l[k]);
        part = l[0];
    }
#pragma unroll
    for (int off = 16; off; off >>= 1)
        part += __shfl_down_sync(0xffffffffu, part, off);
    if ((tid & 31) == 0) sm[SM_RED + (tid >> 5)] = part;
    __syncthreads();
    if (tid == 0) {
        float a = 0.f;
#pragma unroll
        for (int i = 0; i < 8; i++) a += sm[SM_RED + i];
        red1(&sum_out[0], a);
    }
    __syncthreads();   // lat region (H) free before next layer writes H
}

__global__ void __launch_bounds__(256)
k_mlp(const int* __restrict__ s_idx, const int* __restrict__ o_idx,
      const float* __restrict__ nhots,
      const float* __restrict__ W1a, const float* __restrict__ b1a,
      const float* __restrict__ W1b, const float* __restrict__ b1b,
      const float* __restrict__ W2a, const float* __restrict__ b2a,
      const float* __restrict__ W2b, const float* __restrict__ b2b,
      float* __restrict__ lat1, float* __restrict__ lat2,
      float* __restrict__ colsum, float* __restrict__ rowsum) {
    extern __shared__ __align__(16) float sm[];
    int tid = threadIdx.x;
    int e_base = blockIdx.x * 128;

    // ---- stage X [128 edges][64], row pad 65 ----
#pragma unroll
    for (int j = 0; j < 8; j++) {
        int idx4 = tid + 256 * j;            // 0..2047 float4 slots
        int e = idx4 >> 4, kq = idx4 & 15;
        float4 v = make_float4(0.f, 0.f, 0.f, 0.f);
        if (e_base + e < NTt)
            v = __ldg((const float4*)(nhots + (size_t)(e_base + e) * 64) + kq);
        float* dst = sm + SM_X + e * 65 + kq * 4;
        dst[0] = v.x; dst[1] = v.y; dst[2] = v.z; dst[3] = v.w;
    }
    // ---- stage both weight sets ----
    for (int i = tid; i < 4096; i += 256) { sm[SM_W1 + i] = W1a[i]; sm[SM_W2 + i] = W2a[i]; }
    for (int i = tid; i < 1024; i += 256) { sm[SM_W1b + i] = W1b[i]; sm[SM_W2b + i] = W2b[i]; }
    if (tid < 64) { sm[SM_BA1 + tid] = b1a[tid]; sm[SM_BA2 + tid] = b2a[tid]; }
    if (tid < 16) { sm[SM_BB1 + tid] = b1b[tid]; sm[SM_BB2 + tid] = b2b[tid]; }
    __syncthreads();

    mlp_layer(sm, tid, e_base, sm + SM_W1, sm + SM_W1b, sm + SM_BA1, sm + SM_BB1,
              o_idx, lat1, colsum);
    mlp_layer(sm, tid, e_base, sm + SM_W2, sm + SM_W2b, sm + SM_BA2, sm + SM_BB2,
              s_idx, lat2, rowsum);
}

__global__ void k_scatter(const int* __restrict__ s_idx,
                          const int* __restrict__ o_idx) {
    int t = blockIdx.x * blockDim.x + threadIdx.x;
    if (t < NTt) {
        int s = s_idx[t], o = o_idx[t];
        g_perm_s[atomicAdd(&g_cur_s[s], 1)] = t;
        g_perm_o[atomicAdd(&g_cur_o[o], 1)] = t;
    }
}

// ------ layer-1 spmm, warp per o: weights loaded once, red into h[s] ------
// software pipeline: perm 2 ahead, s/lat 1 ahead
__global__ void __launch_bounds__(256)
k_spmm1(const int* __restrict__ s_idx, const float* __restrict__ w1) {
    int w = (blockIdx.x * blockDim.x + threadIdx.x) >> 5;
    int lane = threadIdx.x & 31;
    if (w >= Nn) return;
    int o = w;
    int deg = g_deg_o[o];
    if (deg == 0) return;
    int beg = g_off_o[o], end = beg + deg;

    float wk[16];
#pragma unroll
    for (int k = 0; k < 16; k++) {
        int j = o * k;
        float c = g_colsum[j];                 // uniform across warp -> broadcast
        float inv = (c > 0.f) ? __frcp_rn(c) : 0.f;
        wk[k] = w1[(size_t)j * 32 + lane] * inv;
    }

    int tA = __ldg(&g_perm_o[beg]);
    int tB = (beg + 1 < end) ? __ldg(&g_perm_o[beg + 1]) : tA;
    int s = __ldg(&s_idx[tA]);
    float lv = (lane < 16) ? __ldg(&g_lat1[(size_t)tA * 16 + lane]) : 0.f;
    for (int p = beg; p < end; p++) {
        int tC = (p + 2 < end) ? __ldg(&g_perm_o[p + 2]) : tB;
        int s_n = s; float lv_n = lv;
        if (p + 1 < end) {
            s_n = __ldg(&s_idx[tB]);
            lv_n = (lane < 16) ? __ldg(&g_lat1[(size_t)tB * 16 + lane]) : 0.f;
        }
        float acc = 0.f;
#pragma unroll
        for (int k = 0; k < 16; k++)
            acc += __shfl_sync(0xffffffffu, lv, k) * wk[k];
        red1(&g_h[s * 32 + lane], acc);
        s = s_n; lv = lv_n; tB = tC;
    }
}

// ------------------------- h = relu(h + bias1) -----------------------------
__global__ void k_relu(const float* __restrict__ bias1) {
    int i = blockIdx.x * blockDim.x + threadIdx.x;
    if (i < Nn * Ee)
        g_h[i] = fmaxf(g_h[i] + bias1[i & 31], 0.f);
}

// -------- h2 row j=0 (k=0 bin): block-aggregated global reduction ---------
__global__ void __launch_bounds__(256)
k_h2k0(const int* __restrict__ o_idx) {
    __shared__ float sacc[8][32];
    int lane = threadIdx.x & 31, wid = threadIdx.x >> 5;
    int gw = blockIdx.x * 8 + wid;
    int nw = gridDim.x * 8;
    float acc = 0.f;
    for (int t = gw; t < NTt; t += nw) {
        float l0 = __ldg(&g_lat2[(size_t)t * 16]);
        int o = __ldg(&o_idx[t]);
        acc += l0 * g_h[o * 32 + lane];
    }
    sacc[wid][lane] = acc;
    __syncthreads();
    if (wid == 0) {
        float tot = 0.f;
#pragma unroll
        for (int i = 0; i < 8; i++) tot += sacc[i][lane];
        red1(&g_h2[lane], tot);
    }
}

// --------------- layer-2 spmm into h2 (warp per s, k>=1 only) -------------
// software pipeline: perm 2 ahead, o/lat 1 ahead
__global__ void __launch_bounds__(256)
k_spmm2(const int* __restrict__ o_idx) {
    __shared__ __align__(16) float stage[8][16 * 32];
    int wid = threadIdx.x >> 5, lane = threadIdx.x & 31;
    int s = blockIdx.x * 8 + wid;
    if (s >= Nn) return;
    int deg = g_deg_s[s];
    if (deg == 0) return;
    int beg = g_off_s[s], end = beg + deg;
    float acc[16];
#pragma unroll
    for (int k = 0; k < 16; k++) acc[k] = 0.f;

    int tA = __ldg(&g_perm_s[beg]);
    int tB = (beg + 1 < end) ? __ldg(&g_perm_s[beg + 1]) : tA;
    int o = __ldg(&o_idx[tA]);
    float lv = (lane < 16) ? __ldg(&g_lat2[(size_t)tA * 16 + lane]) : 0.f;
    for (int p = beg; p < end; p++) {
        int tC = (p + 2 < end) ? __ldg(&g_perm_s[p + 2]) : tB;
        int o_n = o; float lv_n = lv;
        if (p + 1 < end) {
            o_n = __ldg(&o_idx[tB]);
            lv_n = (lane < 16) ? __ldg(&g_lat2[(size_t)tB * 16 + lane]) : 0.f;
        }
        float hv = g_h[o * 32 + lane];
#pragma unroll
        for (int k = 1; k < 16; k++)
            acc[k] += __shfl_sync(0xffffffffu, lv, k) * hv;
        o = o_n; lv = lv_n; tB = tC;
    }
    float* st = stage[wid];
#pragma unroll
    for (int k = 1; k < 16; k++) st[k * 32 + lane] = acc[k];
    __syncwarp();
#pragma unroll
    for (int it = 0; it < 4; it++) {
        int idx = it * 32 + lane;        // 0..127 over 16 rows x 8 float4
        if (idx >= 8) {                  // skip k=0 (handled by k_h2k0)
            int k = idx >> 3, q = idx & 7;
            float4 v = ((float4*)st)[idx];
            int j = s * k;
            red4(&((float4*)g_h2)[(size_t)j * 8 + q], v);
        }
    }
}

// ------------------- einsum + bias2: out, 2 nodes / thread ----------------
__global__ void __launch_bounds__(256)
k_out(const float* __restrict__ w2, const float* __restrict__ bias2,
      float* __restrict__ out) {
    extern __shared__ __align__(16) float sw2[];   // 16*32*32 floats = 64 KB
    for (int i = threadIdx.x; i < 16 * 32 * 32; i += 256) sw2[i] = w2[i];
    __syncthreads();
    int n0 = blockIdx.x * 256 + threadIdx.x;       // 0..24999
    if (n0 >= Nn / 2) return;
    int n1 = n0 + Nn / 2;
    ULL accA[16], accB[16];
#pragma unroll
    for (int c2 = 0; c2 < 16; c2++) {
        accA[c2] = ((const ULL*)bias2)[c2];
        accB[c2] = accA[c2];
    }
#pragma unroll 1
    for (int r = 0; r < 16; r++) {
        int jA = r * Nn + n0;
        int jB = jA + Nn / 2;
        float ra = g_rowsum[jA], rb = g_rowsum[jB];
        float invA = (ra > 0.f) ? __frcp_rn(ra) : 0.f;
        float invB = (rb > 0.f) ? __frcp_rn(rb) : 0.f;
        const float4* hA = (const float4*)&g_h2[(size_t)jA * 32];
        const float4* hB = (const float4*)&g_h2[(size_t)jB * 32];
#pragma unroll
        for (int e4 = 0; e4 < 8; e4++) {
            float4 va = hA[e4];
            float4 vb = hB[e4];
            float xa[4] = { va.x * invA, va.y * invA, va.z * invA, va.w * invA };
            float xb[4] = { vb.x * invB, vb.y * invB, vb.z * invB, vb.w * invB };
#pragma unroll
            for (int u = 0; u < 4; u++) {
                int e = e4 * 4 + u;
                ULL sa = splat2(xa[u]);
                ULL sb = splat2(xb[u]);
                const float4* wr4 = (const float4*)&sw2[(r * 32 + e) * 32];
#pragma unroll
                for (int c4 = 0; c4 < 8; c4++) {
                    F4U w; w.f = wr4[c4];
                    accA[2 * c4]     = ffma2(sa, w.u[0], accA[2 * c4]);
                    accA[2 * c4 + 1] = ffma2(sa, w.u[1], accA[2 * c4 + 1]);
                    accB[2 * c4]     = ffma2(sb, w.u[0], accB[2 * c4]);
                    accB[2 * c4 + 1] = ffma2(sb, w.u[1], accB[2 * c4 + 1]);
                }
            }
        }
    }
    ULL* opA = (ULL*)(out + (size_t)n0 * 32);
    ULL* opB = (ULL*)(out + (size_t)n1 * 32);
#pragma unroll
    for (int c2 = 0; c2 < 16; c2++) { opA[c2] = accA[c2]; opB[c2] = accB[c2]; }
}

// ------------------------- launch -----------------------------------------
extern "C" void kernel_launch(void* const* d_in, const int* in_sizes, int n_in,
                              void* d_out, int out_size) {
    const int*   s_idx = (const int*)d_in[0];
    const int*   o_idx = (const int*)d_in[1];
    const float* nhots = (const float*)d_in[2];
    const float* W1a   = (const float*)d_in[3];
    const float* b1a   = (const float*)d_in[4];
    const float* W1b   = (const float*)d_in[5];
    const float* b1b   = (const float*)d_in[6];
    const float* W2a   = (const float*)d_in[7];
    const float* b2a   = (const float*)d_in[8];
    const float* W2b   = (const float*)d_in[9];
    const float* b2b   = (const float*)d_in[10];
    const float* w1    = (const float*)d_in[11];
    const float* w2    = (const float*)d_in[12];
    const float* bias1 = (const float*)d_in[13];
    const float* bias2 = (const float*)d_in[14];
    float* out = (float*)d_out;

    static float* lat1p = nullptr;
    static float* lat2p = nullptr;
    static float* colp = nullptr;
    static float* rowp = nullptr;
    if (!lat1p) {
        cudaGetSymbolAddress((void**)&lat1p, g_lat1);
        cudaGetSymbolAddress((void**)&lat2p, g_lat2);
        cudaGetSymbolAddress((void**)&colp, g_colsum);
        cudaGetSymbolAddress((void**)&rowp, g_rowsum);
        cudaFuncSetAttribute(k_mlp, cudaFuncAttributeMaxDynamicSharedMemorySize,
                             SM_FLOATS * (int)sizeof(float));
        cudaFuncSetAttribute(k_out, cudaFuncAttributeMaxDynamicSharedMemorySize,
                             16 * 32 * 32 * (int)sizeof(float));
    }

    int mlp_blocks = (NTt + 127) / 128;
    size_t mlp_smem = SM_FLOATS * sizeof(float);

    k_init<<<2048, 256>>>();                                   // 0
    k_deg<<<(NTt + 255) / 256, 256>>>(s_idx, o_idx);           // 1
    k_alloc<<<(Nn + 255) / 256, 256>>>();                      // 2
    k_mlp<<<mlp_blocks, 256, mlp_smem>>>(s_idx, o_idx, nhots,  // 3 <- ncu slot
                                         W1a, b1a, W1b, b1b,
                                         W2a, b2a, W2b, b2b,
                                         lat1p, lat2p, colp, rowp);
    k_scatter<<<(NTt + 255) / 256, 256>>>(s_idx, o_idx);       // 4
    k_spmm1<<<(Nn * 32 + 255) / 256, 256>>>(s_idx, w1);        // 5
    k_relu<<<(Nn * Ee + 255) / 256, 256>>>(bias1);             // 6
    k_h2k0<<<512, 256>>>(o_idx);                               // 7
    k_spmm2<<<(Nn + 7) / 8, 256>>>(o_idx);                     // 8
    k_out<<<(Nn / 2 + 255) / 256, 256, 16 * 32 * 32 * (int)sizeof(float)>>>(w2, bias2, out); // 9
}

// round 9
// speedup vs baseline: 1.3262x; 1.1476x over previous
#include <cuda_runtime.h>
#include <cstdint>

#define Nn  50000
#define NTt 300000
#define RPk 16
#define Ee  32
#define Cc  32

// ------------------------- device scratch (static, no allocs) -------------
__device__ float g_lat1[(size_t)NTt * RPk];        // 19.2 MB
__device__ float g_lat2[(size_t)NTt * RPk];        // 19.2 MB
__device__ float g_colsum[Nn * RPk];               // 3.2 MB
__device__ float g_rowsum[Nn * RPk];               // 3.2 MB
__device__ float g_h[Nn * Ee];                     // 6.4 MB
__device__ float g_h2[(size_t)RPk * Nn * Ee];      // 102.4 MB
__device__ int   g_deg_s[Nn];
__device__ int   g_deg_o[Nn];
__device__ int   g_off_s[Nn];
__device__ int   g_off_o[Nn];
__device__ int   g_cur_s[Nn];
__device__ int   g_cur_o[Nn];
__device__ int   g_perm_s[NTt];
__device__ int   g_perm_o[NTt];
__device__ int   g_counter[2];

// ------------------------- small helpers ----------------------------------
typedef unsigned long long ULL;
union F4U { float4 f; ULL u[2]; float s[4]; };

__device__ __forceinline__ ULL splat2(float v) {
    ULL r;
    asm("mov.b64 %0, {%1, %1};" : "=l"(r) : "f"(v));
    return r;
}
__device__ __forceinline__ ULL ffma2(ULL a, ULL b, ULL c) {
    ULL d;
    asm("fma.rn.f32x2 %0, %1, %2, %3;" : "=l"(d) : "l"(a), "l"(b), "l"(c));
    return d;
}
__device__ __forceinline__ void red4(float4* a, float4 v) {
    asm volatile("red.global.add.v4.f32 [%0], {%1, %2, %3, %4};"
                 :: "l"(a), "f"(v.x), "f"(v.y), "f"(v.z), "f"(v.w) : "memory");
}
__device__ __forceinline__ void red1(float* a, float v) {
    asm volatile("red.global.add.f32 [%0], %1;" :: "l"(a), "f"(v) : "memory");
}
// f32 -> tf32 (bits in a b32 reg)
__device__ __forceinline__ unsigned f2t(float f) {
    unsigned r;
    asm("cvt.rna.tf32.f32 %0, %1;" : "=r"(r) : "f"(f));
    return r;
}
// D(16x8,f32) += A(16x8,tf32,row) * B(8x8,tf32,col)
__device__ __forceinline__ void mma8(float* d, unsigned a0, unsigned a1,
                                     unsigned a2, unsigned a3,
                                     unsigned b0, unsigned b1) {
    asm("mma.sync.aligned.m16n8k8.row.col.f32.tf32.tf32.f32 "
        "{%0,%1,%2,%3}, {%4,%5,%6,%7}, {%8,%9}, {%0,%1,%2,%3};"
        : "+f"(d[0]), "+f"(d[1]), "+f"(d[2]), "+f"(d[3])
        : "r"(a0), "r"(a1), "r"(a2), "r"(a3), "r"(b0), "r"(b1));
}

// ------------------------- init: zero scratch -----------------------------
__global__ void k_init() {
    size_t i = (size_t)blockIdx.x * blockDim.x + threadIdx.x;
    size_t stride = (size_t)gridDim.x * blockDim.x;
    float4 z = make_float4(0.f, 0.f, 0.f, 0.f);
    for (size_t p = i; p < (size_t)RPk * Nn * Ee / 4; p += stride)
        ((float4*)g_h2)[p] = z;
    for (size_t p = i; p < (size_t)Nn * RPk / 4; p += stride) {
        ((float4*)g_colsum)[p] = z;
        ((float4*)g_rowsum)[p] = z;
    }
    for (size_t p = i; p < (size_t)Nn * Ee / 4; p += stride)
        ((float4*)g_h)[p] = z;
    for (size_t p = i; p < Nn / 4; p += stride) {
        ((int4*)g_deg_s)[p] = make_int4(0, 0, 0, 0);
        ((int4*)g_deg_o)[p] = make_int4(0, 0, 0, 0);
    }
    if (i == 0) { g_counter[0] = 0; g_counter[1] = 0; }
}

// ------------------------- degree count -----------------------------------
__global__ void k_deg(const int* __restrict__ s_idx, const int* __restrict__ o_idx) {
    int t = blockIdx.x * blockDim.x + threadIdx.x;
    if (t < NTt) {
        atomicAdd(&g_deg_s[s_idx[t]], 1);
        atomicAdd(&g_deg_o[o_idx[t]], 1);
    }
}

// ---------------- CSR range allocation (warp-aggregated, unordered) -------
__global__ void k_alloc() {
    int i = blockIdx.x * blockDim.x + threadIdx.x;
    int lane = threadIdx.x & 31;
    int ds = (i < Nn) ? g_deg_s[i] : 0;
    int dq = (i < Nn) ? g_deg_o[i] : 0;
    int ss = ds, so = dq;
#pragma unroll
    for (int off = 1; off < 32; off <<= 1) {
        int a = __shfl_up_sync(0xffffffffu, ss, off);
        int b = __shfl_up_sync(0xffffffffu, so, off);
        if (lane >= off) { ss += a; so += b; }
    }
    int bs = 0, bo = 0;
    if (lane == 31) {
        bs = atomicAdd(&g_counter[0], ss);
        bo = atomicAdd(&g_counter[1], so);
    }
    bs = __shfl_sync(0xffffffffu, bs, 31);
    bo = __shfl_sync(0xffffffffu, bo, 31);
    if (i < Nn) {
        int es = bs + ss - ds;
        int eo = bo + so - dq;
        g_off_s[i] = es; g_cur_s[i] = es;
        g_off_o[i] = eo; g_cur_o[i] = eo;
    }
}

// --------- fused double-MLP (tf32 tensor cores) + softmax + seg sums ------
// block = 128 edges, 256 threads (8 warps, warp = 16-edge m-stripe).
// smem (32-bit words):
//   X  [128][68] tf32 @ 0      (8704)
//   H  [128][68] tf32 @ 8704   (8704)  -- reused as lat[128][17] f32
//   Wa [64][72]  tf32 @ 17408  (4608)  -- re-staged per layer
//   Wb [64][24]  tf32 @ 22016  (1536)
//   ba [64] f32 @ 23552 ; bb [16] f32 @ 23616 ; red [8] @ 23632
#define SM_X    0
#define SM_H    8704
#define SM_W    17408
#define SM_WB   22016
#define SM_BA   23552
#define SM_BB   23616
#define SM_RED  23632
#define SM_FLOATS 23640

__device__ __forceinline__ void softmax16(float* l) {
    float m = l[0];
#pragma unroll
    for (int k = 1; k < 16; k++) m = fmaxf(m, l[k]);
    float s = 0.f;
#pragma unroll
    for (int k = 0; k < 16; k++) { l[k] = __expf(l[k] - m); s += l[k]; }
    float inv = 1.f / s;
#pragma unroll
    for (int k = 0; k < 16; k++) l[k] *= inv;
}

__device__ __forceinline__ void stage_w(float* sm, int tid,
                                        const float* __restrict__ Wa,
                                        const float* __restrict__ ba,
                                        const float* __restrict__ Wb,
                                        const float* __restrict__ bb) {
    unsigned* Ws  = (unsigned*)(sm + SM_W);
    unsigned* Wbs = (unsigned*)(sm + SM_WB);
    for (int i = tid; i < 4096; i += 256)
        Ws[(i >> 6) * 72 + (i & 63)] = f2t(Wa[i]);
    for (int i = tid; i < 1024; i += 256)
        Wbs[(i >> 4) * 24 + (i & 15)] = f2t(Wb[i]);
    if (tid < 64) sm[SM_BA + tid] = ba[tid];
    if (tid < 16) sm[SM_BB + tid] = bb[tid];
}

__device__ __forceinline__ void mlp_layer(float* sm, int tid, int e_base,
                                          const int* __restrict__ nidx,
                                          float* __restrict__ lat_out,
                                          float* __restrict__ sum_out) {
    int lane = tid & 31, warp = tid >> 5;
    int g = lane >> 2, t4 = lane & 3;
    int m0 = warp * 16;
    const unsigned* Xs  = (const unsigned*)(sm + SM_X);
    const unsigned* Ws  = (const unsigned*)(sm + SM_W);
    const unsigned* Wbs = (const unsigned*)(sm + SM_WB);
    unsigned* Hs = (unsigned*)(sm + SM_H);

    // ---- phase 1: H[128][64] = relu(X @ Wa + ba) via m16n8k8 tf32 ----
    {
        float dacc[8][4];
#pragma unroll
        for (int n = 0; n < 8; n++) {
            float blo = sm[SM_BA + n * 8 + 2 * t4];
            float bhi = sm[SM_BA + n * 8 + 2 * t4 + 1];
            dacc[n][0] = blo; dacc[n][1] = bhi;
            dacc[n][2] = blo; dacc[n][3] = bhi;
        }
#pragma unroll
        for (int k8 = 0; k8 < 8; k8++) {
            int kb = k8 * 8;
            unsigned a0 = Xs[(m0 + g) * 68 + kb + t4];
            unsigned a1 = Xs[(m0 + g + 8) * 68 + kb + t4];
            unsigned a2 = Xs[(m0 + g) * 68 + kb + t4 + 4];
            unsigned a3 = Xs[(m0 + g + 8) * 68 + kb + t4 + 4];
#pragma unroll
            for (int n = 0; n < 8; n++) {
                unsigned b0 = Ws[(kb + t4) * 72 + n * 8 + g];
                unsigned b1 = Ws[(kb + t4 + 4) * 72 + n * 8 + g];
                mma8(dacc[n], a0, a1, a2, a3, b0, b1);
            }
        }
        // relu + cvt to tf32 + store H
#pragma unroll
        for (int n = 0; n < 8; n++) {
            unsigned lo0 = f2t(fmaxf(dacc[n][0], 0.f));
            unsigned lo1 = f2t(fmaxf(dacc[n][1], 0.f));
            unsigned hi0 = f2t(fmaxf(dacc[n][2], 0.f));
            unsigned hi1 = f2t(fmaxf(dacc[n][3], 0.f));
            ULL p0 = (ULL)lo0 | ((ULL)lo1 << 32);
            ULL p1 = (ULL)hi0 | ((ULL)hi1 << 32);
            *(ULL*)&Hs[(m0 + g) * 68 + n * 8 + 2 * t4] = p0;
            *(ULL*)&Hs[(m0 + g + 8) * 68 + n * 8 + 2 * t4] = p1;
        }
    }
    __syncthreads();

    // ---- phase 2: lat[128][16] = H @ Wb + bb ----
    float facc[2][4];
    {
#pragma unroll
        for (int n = 0; n < 2; n++) {
            float blo = sm[SM_BB + n * 8 + 2 * t4];
            float bhi = sm[SM_BB + n * 8 + 2 * t4 + 1];
            facc[n][0] = blo; facc[n][1] = bhi;
            facc[n][2] = blo; facc[n][3] = bhi;
        }
#pragma unroll
        for (int k8 = 0; k8 < 8; k8++) {
            int kb = k8 * 8;
            unsigned a0 = Hs[(m0 + g) * 68 + kb + t4];
            unsigned a1 = Hs[(m0 + g + 8) * 68 + kb + t4];
            unsigned a2 = Hs[(m0 + g) * 68 + kb + t4 + 4];
            unsigned a3 = Hs[(m0 + g + 8) * 68 + kb + t4 + 4];
#pragma unroll
            for (int n = 0; n < 2; n++) {
                unsigned b0 = Wbs[(kb + t4) * 24 + n * 8 + g];
                unsigned b1 = Wbs[(kb + t4 + 4) * 24 + n * 8 + g];
                mma8(facc[n], a0, a1, a2, a3, b0, b1);
            }
        }
    }
    __syncthreads();   // all H reads done before lat overlays H region
    float* latF = sm + SM_H;
#pragma unroll
    for (int n = 0; n < 2; n++) {
        latF[(m0 + g) * 17 + n * 8 + 2 * t4]         = facc[n][0];
        latF[(m0 + g) * 17 + n * 8 + 2 * t4 + 1]     = facc[n][1];
        latF[(m0 + g + 8) * 17 + n * 8 + 2 * t4]     = facc[n][2];
        latF[(m0 + g + 8) * 17 + n * 8 + 2 * t4 + 1] = facc[n][3];
    }
    __syncthreads();

    // ---- epilogue: softmax, emit latents, segment-sum atomics ----
    float part = 0.f;
    if (tid < 128 && e_base + tid < NTt) {
        int e = e_base + tid;
        float l[16];
        const float* lr = sm + SM_H + tid * 17;
#pragma unroll
        for (int c = 0; c < 16; c++) l[c] = lr[c];
        softmax16(l);
        float4* po = (float4*)(lat_out + (size_t)e * 16);
#pragma unroll
        for (int q = 0; q < 4; q++)
            po[q] = make_float4(l[4 * q], l[4 * q + 1], l[4 * q + 2], l[4 * q + 3]);
        int ix = nidx[e];
#pragma unroll
        for (int k = 1; k < 16; k++)
            red1(&sum_out[ix * k], l[k]);
        part = l[0];
    }
#pragma unroll
    for (int off = 16; off; off >>= 1)
        part += __shfl_down_sync(0xffffffffu, part, off);
    if ((tid & 31) == 0) sm[SM_RED + (tid >> 5)] = part;
    __syncthreads();
    if (tid == 0) {
        float a = 0.f;
#pragma unroll
        for (int i = 0; i < 8; i++) a += sm[SM_RED + i];
        red1(&sum_out[0], a);
    }
    __syncthreads();   // lat region (H) free before next layer writes H
}

__global__ void __launch_bounds__(256)
k_mlp(const int* __restrict__ s_idx, const int* __restrict__ o_idx,
      const float* __restrict__ nhots,
      const float* __restrict__ W1a, const float* __restrict__ b1a,
      const float* __restrict__ W1b, const float* __restrict__ b1b,
      const float* __restrict__ W2a, const float* __restrict__ b2a,
      const float* __restrict__ W2b, const float* __restrict__ b2b,
      float* __restrict__ lat1, float* __restrict__ lat2,
      float* __restrict__ colsum, float* __restrict__ rowsum) {
    extern __shared__ __align__(16) float sm[];
    int tid = threadIdx.x;
    int e_base = blockIdx.x * 128;

    // ---- stage X [128 edges][64] as tf32, row pad 68 (17 uint4) ----
    unsigned* Xs = (unsigned*)(sm + SM_X);
#pragma unroll
    for (int j = 0; j < 8; j++) {
        int idx4 = tid + 256 * j;            // 0..2047 float4 slots
        int e = idx4 >> 4, kq = idx4 & 15;
        float4 v = make_float4(0.f, 0.f, 0.f, 0.f);
        if (e_base + e < NTt)
            v = __ldg((const float4*)(nhots + (size_t)(e_base + e) * 64) + kq);
        uint4 t;
        t.x = f2t(v.x); t.y = f2t(v.y); t.z = f2t(v.z); t.w = f2t(v.w);
        *(uint4*)&Xs[e * 68 + kq * 4] = t;
    }
    stage_w(sm, tid, W1a, b1a, W1b, b1b);
    __syncthreads();

    mlp_layer(sm, tid, e_base, o_idx, lat1, colsum);

    stage_w(sm, tid, W2a, b2a, W2b, b2b);
    __syncthreads();

    mlp_layer(sm, tid, e_base, s_idx, lat2, rowsum);
}

__global__ void k_scatter(const int* __restrict__ s_idx,
                          const int* __restrict__ o_idx) {
    int t = blockIdx.x * blockDim.x + threadIdx.x;
    if (t < NTt) {
        int s = s_idx[t], o = o_idx[t];
        g_perm_s[atomicAdd(&g_cur_s[s], 1)] = t;
        g_perm_o[atomicAdd(&g_cur_o[o], 1)] = t;
    }
}

// ------ layer-1 spmm, warp per o: weights loaded once, red into h[s] ------
__global__ void __launch_bounds__(256)
k_spmm1(const int* __restrict__ s_idx, const float* __restrict__ w1) {
    int w = (blockIdx.x * blockDim.x + threadIdx.x) >> 5;
    int lane = threadIdx.x & 31;
    if (w >= Nn) return;
    int o = w;
    int deg = g_deg_o[o];
    if (deg == 0) return;
    int beg = g_off_o[o], end = beg + deg;

    float wk[16];
#pragma unroll
    for (int k = 0; k < 16; k++) {
        int j = o * k;
        float c = g_colsum[j];                 // uniform across warp -> broadcast
        float inv = (c > 0.f) ? __frcp_rn(c) : 0.f;
        wk[k] = w1[(size_t)j * 32 + lane] * inv;
    }

    int tA = __ldg(&g_perm_o[beg]);
    int tB = (beg + 1 < end) ? __ldg(&g_perm_o[beg + 1]) : tA;
    int s = __ldg(&s_idx[tA]);
    float lv = (lane < 16) ? __ldg(&g_lat1[(size_t)tA * 16 + lane]) : 0.f;
    for (int p = beg; p < end; p++) {
        int tC = (p + 2 < end) ? __ldg(&g_perm_o[p + 2]) : tB;
        int s_n = s; float lv_n = lv;
        if (p + 1 < end) {
            s_n = __ldg(&s_idx[tB]);
            lv_n = (lane < 16) ? __ldg(&g_lat1[(size_t)tB * 16 + lane]) : 0.f;
        }
        float acc = 0.f;
#pragma unroll
        for (int k = 0; k < 16; k++)
            acc += __shfl_sync(0xffffffffu, lv, k) * wk[k];
        red1(&g_h[s * 32 + lane], acc);
        s = s_n; lv = lv_n; tB = tC;
    }
}

// ------------------------- h = relu(h + bias1) -----------------------------
__global__ void k_relu(const float* __restrict__ bias1) {
    int i = blockIdx.x * blockDim.x + threadIdx.x;
    if (i < Nn * Ee)
        g_h[i] = fmaxf(g_h[i] + bias1[i & 31], 0.f);
}

// -------- h2 row j=0 (k=0 bin): block-aggregated global reduction ---------
__global__ void __launch_bounds__(256)
k_h2k0(const int* __restrict__ o_idx) {
    __shared__ float sacc[8][32];
    int lane = threadIdx.x & 31, wid = threadIdx.x >> 5;
    int gw = blockIdx.x * 8 + wid;
    int nw = gridDim.x * 8;
    float acc = 0.f;
    for (int t = gw; t < NTt; t += nw) {
        float l0 = __ldg(&g_lat2[(size_t)t * 16]);
        int o = __ldg(&o_idx[t]);
        acc += l0 * g_h[o * 32 + lane];
    }
    sacc[wid][lane] = acc;
    __syncthreads();
    if (wid == 0) {
        float tot = 0.f;
#pragma unroll
        for (int i = 0; i < 8; i++) tot += sacc[i][lane];
        red1(&g_h2[lane], tot);
    }
}

// --------------- layer-2 spmm into h2 (warp per s, k>=1 only) -------------
__global__ void __launch_bounds__(256)
k_spmm2(const int* __restrict__ o_idx) {
    __shared__ __align__(16) float stage[8][16 * 32];
    int wid = threadIdx.x >> 5, lane = threadIdx.x & 31;
    int s = blockIdx.x * 8 + wid;
    if (s >= Nn) return;
    int deg = g_deg_s[s];
    if (deg == 0) return;
    int beg = g_off_s[s], end = beg + deg;
    float acc[16];
#pragma unroll
    for (int k = 0; k < 16; k++) acc[k] = 0.f;

    int tA = __ldg(&g_perm_s[beg]);
    int tB = (beg + 1 < end) ? __ldg(&g_perm_s[beg + 1]) : tA;
    int o = __ldg(&o_idx[tA]);
    float lv = (lane < 16) ? __ldg(&g_lat2[(size_t)tA * 16 + lane]) : 0.f;
    for (int p = beg; p < end; p++) {
        int tC = (p + 2 < end) ? __ldg(&g_perm_s[p + 2]) : tB;
        int o_n = o; float lv_n = lv;
        if (p + 1 < end) {
            o_n = __ldg(&o_idx[tB]);
            lv_n = (lane < 16) ? __ldg(&g_lat2[(size_t)tB * 16 + lane]) : 0.f;
        }
        float hv = g_h[o * 32 + lane];
#pragma unroll
        for (int k = 1; k < 16; k++)
            acc[k] += __shfl_sync(0xffffffffu, lv, k) * hv;
        o = o_n; lv = lv_n; tB = tC;
    }
    float* st = stage[wid];
#pragma unroll
    for (int k = 1; k < 16; k++) st[k * 32 + lane] = acc[k];
    __syncwarp();
#pragma unroll
    for (int it = 0; it < 4; it++) {
        int idx = it * 32 + lane;        // 0..127 over 16 rows x 8 float4
        if (idx >= 8) {                  // skip k=0 (handled by k_h2k0)
            int k = idx >> 3, q = idx & 7;
            float4 v = ((float4*)st)[idx];
            int j = s * k;
            red4(&((float4*)g_h2)[(size_t)j * 8 + q], v);
        }
    }
}

// ------------------- einsum + bias2: out, 2 nodes / thread ----------------
__global__ void __launch_bounds__(256)
k_out(const float* __restrict__ w2, const float* __restrict__ bias2,
      float* __restrict__ out) {
    extern __shared__ __align__(16) float sw2[];   // 16*32*32 floats = 64 KB
    for (int i = threadIdx.x; i < 16 * 32 * 32; i += 256) sw2[i] = w2[i];
    __syncthreads();
    int n0 = blockIdx.x * 256 + threadIdx.x;       // 0..24999
    if (n0 >= Nn / 2) return;
    int n1 = n0 + Nn / 2;
    ULL accA[16], accB[16];
#pragma unroll
    for (int c2 = 0; c2 < 16; c2++) {
        accA[c2] = ((const ULL*)bias2)[c2];
        accB[c2] = accA[c2];
    }
#pragma unroll 1
    for (int r = 0; r < 16; r++) {
        int jA = r * Nn + n0;
        int jB = jA + Nn / 2;
        float ra = g_rowsum[jA], rb = g_rowsum[jB];
        float invA = (ra > 0.f) ? __frcp_rn(ra) : 0.f;
        float invB = (rb > 0.f) ? __frcp_rn(rb) : 0.f;
        const float4* hA = (const float4*)&g_h2[(size_t)jA * 32];
        const float4* hB = (const float4*)&g_h2[(size_t)jB * 32];
#pragma unroll
        for (int e4 = 0; e4 < 8; e4++) {
            float4 va = hA[e4];
            float4 vb = hB[e4];
            float xa[4] = { va.x * invA, va.y * invA, va.z * invA, va.w * invA };
            float xb[4] = { vb.x * invB, vb.y * invB, vb.z * invB, vb.w * invB };
#pragma unroll
            for (int u = 0; u < 4; u++) {
                int e = e4 * 4 + u;
                ULL sa = splat2(xa[u]);
                ULL sb = splat2(xb[u]);
                const float4* wr4 = (const float4*)&sw2[(r * 32 + e) * 32];
#pragma unroll
                for (int c4 = 0; c4 < 8; c4++) {
                    F4U w; w.f = wr4[c4];
                    accA[2 * c4]     = ffma2(sa, w.u[0], accA[2 * c4]);
                    accA[2 * c4 + 1] = ffma2(sa, w.u[1], accA[2 * c4 + 1]);
                    accB[2 * c4]     = ffma2(sb, w.u[0], accB[2 * c4]);
                    accB[2 * c4 + 1] = ffma2(sb, w.u[1], accB[2 * c4 + 1]);
                }
            }
        }
    }
    ULL* opA = (ULL*)(out + (size_t)n0 * 32);
    ULL* opB = (ULL*)(out + (size_t)n1 * 32);
#pragma unroll
    for (int c2 = 0; c2 < 16; c2++) { opA[c2] = accA[c2]; opB[c2] = accB[c2]; }
}

// ------------------------- launch -----------------------------------------
extern "C" void kernel_launch(void* const* d_in, const int* in_sizes, int n_in,
                              void* d_out, int out_size) {
    const int*   s_idx = (const int*)d_in[0];
    const int*   o_idx = (const int*)d_in[1];
    const float* nhots = (const float*)d_in[2];
    const float* W1a   = (const float*)d_in[3];
    const float* b1a   = (const float*)d_in[4];
    const float* W1b   = (const float*)d_in[5];
    const float* b1b   = (const float*)d_in[6];
    const float* W2a   = (const float*)d_in[7];
    const float* b2a   = (const float*)d_in[8];
    const float* W2b   = (const float*)d_in[9];
    const float* b2b   = (const float*)d_in[10];
    const float* w1    = (const float*)d_in[11];
    const float* w2    = (const float*)d_in[12];
    const float* bias1 = (const float*)d_in[13];
    const float* bias2 = (const float*)d_in[14];
    float* out = (float*)d_out;

    static float* lat1p = nullptr;
    static float* lat2p = nullptr;
    static float* colp = nullptr;
    static float* rowp = nullptr;
    if (!lat1p) {
        cudaGetSymbolAddress((void**)&lat1p, g_lat1);
        cudaGetSymbolAddress((void**)&lat2p, g_lat2);
        cudaGetSymbolAddress((void**)&colp, g_colsum);
        cudaGetSymbolAddress((void**)&rowp, g_rowsum);
        cudaFuncSetAttribute(k_mlp, cudaFuncAttributeMaxDynamicSharedMemorySize,
                             SM_FLOATS * (int)sizeof(float));
        cudaFuncSetAttribute(k_out, cudaFuncAttributeMaxDynamicSharedMemorySize,
                             16 * 32 * 32 * (int)sizeof(float));
    }

    int mlp_blocks = (NTt + 127) / 128;
    size_t mlp_smem = SM_FLOATS * sizeof(float);

    k_init<<<2048, 256>>>();                                   // 0
    k_deg<<<(NTt + 255) / 256, 256>>>(s_idx, o_idx);           // 1
    k_alloc<<<(Nn + 255) / 256, 256>>>();                      // 2
    k_mlp<<<mlp_blocks, 256, mlp_smem>>>(s_idx, o_idx, nhots,  // 3 <- ncu slot
                                         W1a, b1a, W1b, b1b,
                                         W2a, b2a, W2b, b2b,
                                         lat1p, lat2p, colp, rowp);
    k_scatter<<<(NTt + 255) / 256, 256>>>(s_idx, o_idx);       // 4
    k_spmm1<<<(Nn * 32 + 255) / 256, 256>>>(s_idx, w1);        // 5
    k_relu<<<(Nn * Ee + 255) / 256, 256>>>(bias1);             // 6
    k_h2k0<<<512, 256>>>(o_idx);                               // 7
    k_spmm2<<<(Nn + 7) / 8, 256>>>(o_idx);                     // 8
    k_out<<<(Nn / 2 + 255) / 256, 256, 16 * 32 * 32 * (int)sizeof(float)>>>(w2, bias2, out); // 9
}